// round 8
// baseline (speedup 1.0000x reference)
#include <cuda_runtime.h>
#include <cuda_bf16.h>
#include <cuda_fp8.h>
#include <math.h>
#include <stdint.h>

// Shapes
#define NB   64
#define T1   33
#define TL   32
#define I1   197
#define IP   224      // padded i
#define CD   512
#define TEMP 0.07f
#define NCH  4        // K chunks of 128 (fp8: 128B rows)
#define A_CH 8192     // A chunk image: 64 rows x 128B
#define B_CH 28672    // B chunk image: 224 rows x 128B
#define NCTA 2048     // 32 x 64

// Scratch: pre-swizzled, chunk-major fp8 SMEM images
__device__ __align__(256) uint8_t g_Asw[32 * NCH * A_CH];
__device__ __align__(256) uint8_t g_Bsw[NB * NCH * B_CH];
__device__ float g_tti[NB * NB];
__device__ int   g_cnt;

// ---------------------------------------------------------------------------
// Portable PTX helpers
// ---------------------------------------------------------------------------
__device__ __forceinline__ uint32_t smem_u32(const void* p) {
    uint32_t a;
    asm("{ .reg .u64 t; cvta.to.shared.u64 t, %1; cvt.u32.u64 %0, t; }"
        : "=r"(a) : "l"(p));
    return a;
}
#define SWZ(o) ((o) ^ ((((uint32_t)(o)) >> 3) & 0x70u))

__device__ __forceinline__ void bulk_ld(uint32_t dst, const void* src,
                                        uint32_t bytes, uint32_t mbar) {
    asm volatile(
        "cp.async.bulk.shared::cluster.global.mbarrier::complete_tx::bytes "
        "[%0], [%1], %2, [%3];"
        :: "r"(dst), "l"(src), "r"(bytes), "r"(mbar) : "memory");
}
__device__ __forceinline__ void mbar_init(uint32_t m, uint32_t cnt) {
    asm volatile("mbarrier.init.shared.b64 [%0], %1;" :: "r"(m), "r"(cnt) : "memory");
}
__device__ __forceinline__ void mbar_expect(uint32_t m, uint32_t bytes) {
    asm volatile("mbarrier.arrive.expect_tx.shared.b64 _, [%0], %1;"
                 :: "r"(m), "r"(bytes) : "memory");
}
__device__ __forceinline__ void mbar_arrive(uint32_t m) {
    asm volatile("mbarrier.arrive.shared.b64 _, [%0];" :: "r"(m) : "memory");
}
#define MBAR_WAIT(addr, par) do {                                               \
    uint32_t _m = (addr), _p = (par), _d;                                       \
    asm volatile("{\n\t.reg .pred p;\n\t"                                       \
        "mbarrier.try_wait.parity.acquire.cta.shared::cta.b64 p, [%1], %2;\n\t" \
        "selp.b32 %0, 1, 0, p;\n\t}" : "=r"(_d) : "r"(_m), "r"(_p) : "memory"); \
    if (!_d) {                                                                  \
        asm volatile("{\n\t.reg .pred P1;\n\tWL_%=:\n\t"                        \
            "mbarrier.try_wait.parity.acquire.cta.shared::cta.b64 P1, [%0], %1, 0x989680;\n\t" \
            "@P1 bra.uni WD_%=;\n\tbra.uni WL_%=;\n\tWD_%=:\n\t}"               \
            :: "r"(_m), "r"(_p) : "memory");                                    \
    }                                                                           \
} while (0)

__device__ __forceinline__ void ldm_x4(uint32_t& r0, uint32_t& r1,
                                       uint32_t& r2, uint32_t& r3, uint32_t a) {
    asm volatile("ldmatrix.sync.aligned.m8n8.x4.shared.b16 {%0,%1,%2,%3}, [%4];"
                 : "=r"(r0), "=r"(r1), "=r"(r2), "=r"(r3) : "r"(a));
}
__device__ __forceinline__ void ldm_x2(uint32_t& r0, uint32_t& r1, uint32_t a) {
    asm volatile("ldmatrix.sync.aligned.m8n8.x2.shared.b16 {%0,%1}, [%2];"
                 : "=r"(r0), "=r"(r1) : "r"(a));
}
// fp8 e4m3 MMA, K=32 per instruction (sm_89+ base PTX)
__device__ __forceinline__ void mma_fp8(float* d, const uint32_t* a,
                                        uint32_t b0, uint32_t b1) {
    asm volatile(
        "mma.sync.aligned.m16n8k32.row.col.f32.e4m3.e4m3.f32 "
        "{%0,%1,%2,%3}, {%4,%5,%6,%7}, {%8,%9}, {%0,%1,%2,%3};"
        : "+f"(d[0]), "+f"(d[1]), "+f"(d[2]), "+f"(d[3])
        : "r"(a[0]), "r"(a[1]), "r"(a[2]), "r"(a[3]), "r"(b0), "r"(b1));
}

__device__ __forceinline__ uint8_t to_fp8(float v) {
    return (uint8_t)__nv_cvt_float_to_fp8(v, __NV_SATFINITE, __NV_E4M3);
}

// ---------------------------------------------------------------------------
// knorm: grid (64,2), block 512. by==0 -> text, by==1 -> video. fp8 output,
// written directly in swizzled chunk-major (K=128) SMEM image.
// ---------------------------------------------------------------------------
__global__ void knorm(const float* __restrict__ text, const float* __restrict__ video) {
    int b = blockIdx.x, d = threadIdx.x;
    if (blockIdx.y == 0) {
        if (b == 0 && d == 0) g_cnt = 0;
        const float* p = text + (size_t)b * T1 * CD + d;
        float s = 0.f;
#pragma unroll
        for (int t = 0; t < T1; t++) { float v = p[t * CD]; s += v * v; }
        float inv = 1.0f / sqrtf(s);
        uint8_t* base = g_Asw + (((size_t)(b >> 1)) * NCH + (d >> 7)) * A_CH;
        uint32_t colb = d & 127;
#pragma unroll 4
        for (int t = 0; t < TL; t++) {
            int row = (b & 1) * 32 + t;
            base[SWZ(row * 128 + colb)] = to_fp8(p[(t + 1) * CD] * inv);
        }
    } else {
        const float* p = video + (size_t)b * I1 * CD + d;
        float s = 0.f;
#pragma unroll 4
        for (int t = 0; t < I1; t++) { float v = p[t * CD]; s += v * v; }
        float inv = 1.0f / sqrtf(s);
        uint8_t* base = g_Bsw + ((size_t)b * NCH + (d >> 7)) * B_CH;
        uint32_t colb = d & 127;
        for (int t = 0; t < I1; t++)
            base[SWZ(t * 128 + colb)] = to_fp8(p[t * CD] * inv);
        for (int t = I1; t < IP; t++)
            base[SWZ(t * 128 + colb)] = 0;
    }
}

// ---------------------------------------------------------------------------
// ksim: CTA (qh,y): D[64,224] = A(64x512)*B(224x512)^T in e4m3->f32.
// 8 warps 2(M)x4(N), warp tile 32x56, K-chunks of 128 (4 x k32 steps),
// 3-stage bulk ring, occupancy 2. Fused max/mean epilogue + last-CTA loss.
// ---------------------------------------------------------------------------
#define SM_RMAX  0
#define SM_MBF   1024
#define SM_MBE   1088
#define SM_STG   2048
#define STG_SZ   (A_CH + B_CH)              // 36864
#define SM_TOTAL (SM_STG + 3 * STG_SZ)      // 112640

__global__ void __launch_bounds__(256, 2)
ksim(const int* __restrict__ amask, float* __restrict__ out) {
    extern __shared__ char smem[];
    __shared__ int lastflag;
    const uint32_t sb = smem_u32(smem);
    const int tid = threadIdx.x, wid = tid >> 5, lid = tid & 31;
    const int wm = wid & 1, wn = wid >> 1;
    const int qh = blockIdx.x, y = blockIdx.y;

    const uint8_t* Asrc = g_Asw + (size_t)qh * NCH * A_CH;
    const uint8_t* Bsrc = g_Bsw + (size_t)y * NCH * B_CH;

    if (tid == 0) {
#pragma unroll
        for (int s = 0; s < 3; s++) {
            mbar_init(sb + SM_MBF + 8 * s, 1);
            mbar_init(sb + SM_MBE + 8 * s, 8);
        }
    }
    __syncthreads();
    if (tid == 0) {
#pragma unroll
        for (int s = 0; s < 3; s++) {                 // prologue: chunks 0..2
            uint32_t mb = sb + SM_MBF + 8 * s;
            uint32_t st = sb + SM_STG + s * STG_SZ;
            mbar_expect(mb, STG_SZ);
            bulk_ld(st,        Asrc + (size_t)s * A_CH, A_CH, mb);
            bulk_ld(st + A_CH, Bsrc + (size_t)s * B_CH, B_CH, mb);
        }
    }

    float acc[2][7][4];
#pragma unroll
    for (int mi = 0; mi < 2; mi++)
#pragma unroll
        for (int nj = 0; nj < 7; nj++)
#pragma unroll
            for (int d = 0; d < 4; d++) acc[mi][nj][d] = 0.f;

    const int arow = 32 * wm + (lid & 15);
    const int brow = 56 * wn + (lid & 15);
    const int btr  = 56 * wn + 48 + (lid & 7);
    const int chi  = (lid >> 4) * 16;
    const int cht  = ((lid >> 3) & 1) * 16;

    int cs = 0;
    uint32_t ph = 0, eph = 0;

#pragma unroll 1
    for (int c = 0; c < NCH; c++) {
        const int s = cs;
        cs = (cs == 2) ? 0 : cs + 1;
        MBAR_WAIT(sb + SM_MBF + 8 * s, (ph >> s) & 1);
        ph ^= (1u << s);
        const uint32_t Abase = sb + SM_STG + s * STG_SZ;
        const uint32_t Bbase = Abase + A_CH;

#pragma unroll
        for (int ks = 0; ks < 4; ks++) {              // k32 steps within K=128
            const int kb = ks * 32;                   // byte offset within row
            uint32_t af[2][4];
#pragma unroll
            for (int mi = 0; mi < 2; mi++)
                ldm_x4(af[mi][0], af[mi][1], af[mi][2], af[mi][3],
                       Abase + SWZ((arow + 16 * mi) * 128 + kb + chi));
            uint32_t bf[3][4], bt[2];
#pragma unroll
            for (int ni = 0; ni < 3; ni++)
                ldm_x4(bf[ni][0], bf[ni][1], bf[ni][2], bf[ni][3],
                       Bbase + SWZ((brow + 16 * ni) * 128 + kb + chi));
            ldm_x2(bt[0], bt[1], Bbase + SWZ(btr * 128 + kb + cht));
#pragma unroll
            for (int mi = 0; mi < 2; mi++) {
#pragma unroll
                for (int ni = 0; ni < 3; ni++) {
                    mma_fp8(acc[mi][2 * ni],     af[mi], bf[ni][0], bf[ni][2]);
                    mma_fp8(acc[mi][2 * ni + 1], af[mi], bf[ni][1], bf[ni][3]);
                }
                mma_fp8(acc[mi][6], af[mi], bt[0], bt[1]);
            }
        }
        if (lid == 0) mbar_arrive(sb + SM_MBE + 8 * s);

        if (tid == 0 && c < NCH - 3) {                // refill stage s, chunk c+3
            MBAR_WAIT(sb + SM_MBE + 8 * s, (eph >> s) & 1);
            eph ^= (1u << s);
            uint32_t mb = sb + SM_MBF + 8 * s;
            mbar_expect(mb, STG_SZ);
            bulk_ld(Abase,        Asrc + (size_t)(c + 3) * A_CH, A_CH, mb);
            bulk_ld(Abase + A_CH, Bsrc + (size_t)(c + 3) * B_CH, B_CH, mb);
        }
    }

    // ---- Epilogue: per-row max over i (mask i>=197) -> masked mean over t
    float* rowmax = (float*)(smem + SM_RMAX);          // [64][4]
#pragma unroll
    for (int mi = 0; mi < 2; mi++)
#pragma unroll
        for (int h = 0; h < 2; h++) {
            float m = -3.4e38f;
#pragma unroll
            for (int nj = 0; nj < 7; nj++)
#pragma unroll
                for (int e = 0; e < 2; e++) {
                    int col = 56 * wn + 8 * nj + 2 * (lid & 3) + e;
                    float v = acc[mi][nj][2 * h + e];
                    if (col < I1) m = fmaxf(m, v);
                }
            m = fmaxf(m, __shfl_xor_sync(0xffffffffu, m, 1));
            m = fmaxf(m, __shfl_xor_sync(0xffffffffu, m, 2));
            if ((lid & 3) == 0) {
                int row = 32 * wm + 16 * mi + 8 * h + (lid >> 2);
                rowmax[4 * row + wn] = m;
            }
        }
    __syncthreads();

    if (tid < 64) {
        int row = tid;
        float m = fmaxf(fmaxf(rowmax[4 * row], rowmax[4 * row + 1]),
                        fmaxf(rowmax[4 * row + 2], rowmax[4 * row + 3]));
        int xl = row >> 5, t = row & 31;
        int x = 2 * qh + xl;
        int mk = amask[x * T1 + 1 + t] != 0;
        float v = mk ? m * TEMP : 0.f;
        float cnt = mk ? 1.f : 0.f;
#pragma unroll
        for (int o = 16; o > 0; o >>= 1) {
            v   += __shfl_xor_sync(0xffffffffu, v, o);
            cnt += __shfl_xor_sync(0xffffffffu, cnt, o);
        }
        if (t == 0) g_tti[x * NB + y] = v / fmaxf(cnt, 1e-6f);
    }
    __syncthreads();

    // ---- Last CTA computes the loss
    if (tid == 0) {
        __threadfence();
        lastflag = (atomicAdd(&g_cnt, 1) == NCTA - 1);
    }
    __syncthreads();
    if (lastflag) {
        __threadfence();
        float* sl = (float*)(smem + SM_RMAX);
#pragma unroll 1
        for (int rep = 0; rep < 8; rep++) {
            int x = 8 * wid + rep;
            const float* row = g_tti + x * NB;
            float e = expf(row[lid]) + expf(row[lid + 32]);
#pragma unroll
            for (int o = 16; o > 0; o >>= 1) e += __shfl_xor_sync(0xffffffffu, e, o);
            if (lid == 0) sl[x] = -logf(expf(row[x]) / e + 1e-20f);
        }
        __syncthreads();
        if (tid < 32) {
            float s = sl[lid] + sl[lid + 32];
#pragma unroll
            for (int o = 16; o > 0; o >>= 1) s += __shfl_xor_sync(0xffffffffu, s, o);
            if (lid == 0) out[0] = s * (1.0f / NB);
        }
    }
}

// ---------------------------------------------------------------------------
extern "C" void kernel_launch(void* const* d_in, const int* in_sizes, int n_in,
                              void* d_out, int out_size) {
    const float* text  = (const float*)d_in[0];
    const float* video = (const float*)d_in[1];
    const int*   mask  = (const int*)d_in[2];

    static int smem_set = 0;
    if (!smem_set) {
        cudaFuncSetAttribute(ksim, cudaFuncAttributeMaxDynamicSharedMemorySize, SM_TOTAL);
        smem_set = 1;
    }

    knorm<<<dim3(NB, 2), 512>>>(text, video);
    ksim<<<dim3(32, NB), 256, SM_TOTAL>>>(mask, (float*)d_out);
}

// round 10
// speedup vs baseline: 1.6943x; 1.6943x over previous
#include <cuda_runtime.h>
#include <cuda_bf16.h>
#include <math.h>
#include <stdint.h>

// Shapes
#define NB   64
#define T1   33
#define TL   32
#define I1   197
#define IP   224      // padded i
#define CD   512
#define TEMP 0.07f
#define QS   127.0f   // int8 quant scale (|v| <= 1 guaranteed by normalization)
#define OSCALE (TEMP / (QS * QS))
#define NCH  4        // K chunks of 128 (int8: 128B rows)
#define A_CH 8192     // A chunk image: 64 rows x 128B
#define B_CH 28672    // B chunk image: 224 rows x 128B
#define NCTA 2048     // 32 x 64

// Scratch: pre-swizzled, chunk-major int8 SMEM images
__device__ __align__(256) int8_t g_Asw[32 * NCH * A_CH];
__device__ __align__(256) int8_t g_Bsw[NB * NCH * B_CH];
__device__ float g_tti[NB * NB];
__device__ int   g_cnt;

// ---------------------------------------------------------------------------
// Portable PTX helpers
// ---------------------------------------------------------------------------
__device__ __forceinline__ uint32_t smem_u32(const void* p) {
    uint32_t a;
    asm("{ .reg .u64 t; cvta.to.shared.u64 t, %1; cvt.u32.u64 %0, t; }"
        : "=r"(a) : "l"(p));
    return a;
}
#define SWZ(o) ((o) ^ ((((uint32_t)(o)) >> 3) & 0x70u))

__device__ __forceinline__ void bulk_ld(uint32_t dst, const void* src,
                                        uint32_t bytes, uint32_t mbar) {
    asm volatile(
        "cp.async.bulk.shared::cluster.global.mbarrier::complete_tx::bytes "
        "[%0], [%1], %2, [%3];"
        :: "r"(dst), "l"(src), "r"(bytes), "r"(mbar) : "memory");
}
__device__ __forceinline__ void mbar_init(uint32_t m, uint32_t cnt) {
    asm volatile("mbarrier.init.shared.b64 [%0], %1;" :: "r"(m), "r"(cnt) : "memory");
}
__device__ __forceinline__ void mbar_expect(uint32_t m, uint32_t bytes) {
    asm volatile("mbarrier.arrive.expect_tx.shared.b64 _, [%0], %1;"
                 :: "r"(m), "r"(bytes) : "memory");
}
__device__ __forceinline__ void mbar_arrive(uint32_t m) {
    asm volatile("mbarrier.arrive.shared.b64 _, [%0];" :: "r"(m) : "memory");
}
#define MBAR_WAIT(addr, par) do {                                               \
    uint32_t _m = (addr), _p = (par), _d;                                       \
    asm volatile("{\n\t.reg .pred p;\n\t"                                       \
        "mbarrier.try_wait.parity.acquire.cta.shared::cta.b64 p, [%1], %2;\n\t" \
        "selp.b32 %0, 1, 0, p;\n\t}" : "=r"(_d) : "r"(_m), "r"(_p) : "memory"); \
    if (!_d) {                                                                  \
        asm volatile("{\n\t.reg .pred P1;\n\tWL_%=:\n\t"                        \
            "mbarrier.try_wait.parity.acquire.cta.shared::cta.b64 P1, [%0], %1, 0x989680;\n\t" \
            "@P1 bra.uni WD_%=;\n\tbra.uni WL_%=;\n\tWD_%=:\n\t}"               \
            :: "r"(_m), "r"(_p) : "memory");                                    \
    }                                                                           \
} while (0)

__device__ __forceinline__ void ldm_x4(uint32_t& r0, uint32_t& r1,
                                       uint32_t& r2, uint32_t& r3, uint32_t a) {
    asm volatile("ldmatrix.sync.aligned.m8n8.x4.shared.b16 {%0,%1,%2,%3}, [%4];"
                 : "=r"(r0), "=r"(r1), "=r"(r2), "=r"(r3) : "r"(a));
}
__device__ __forceinline__ void ldm_x2(uint32_t& r0, uint32_t& r1, uint32_t a) {
    asm volatile("ldmatrix.sync.aligned.m8n8.x2.shared.b16 {%0,%1}, [%2];"
                 : "=r"(r0), "=r"(r1) : "r"(a));
}
// int8 IMMA, K=32 per instruction (sm_75+ base PTX, native SASS lineage)
__device__ __forceinline__ void mma_s8(int* d, const uint32_t* a,
                                       uint32_t b0, uint32_t b1) {
    asm volatile(
        "mma.sync.aligned.m16n8k32.row.col.s32.s8.s8.s32 "
        "{%0,%1,%2,%3}, {%4,%5,%6,%7}, {%8,%9}, {%0,%1,%2,%3};"
        : "+r"(d[0]), "+r"(d[1]), "+r"(d[2]), "+r"(d[3])
        : "r"(a[0]), "r"(a[1]), "r"(a[2]), "r"(a[3]), "r"(b0), "r"(b1));
}

__device__ __forceinline__ int8_t to_s8(float v) {
    return (int8_t)__float2int_rn(v * QS);
}

// ---------------------------------------------------------------------------
// knorm: grid (64,2), block 512. by==0 -> text, by==1 -> video. int8 output,
// written directly in swizzled chunk-major (K=128) SMEM image.
// ---------------------------------------------------------------------------
__global__ void knorm(const float* __restrict__ text, const float* __restrict__ video) {
    int b = blockIdx.x, d = threadIdx.x;
    if (blockIdx.y == 0) {
        if (b == 0 && d == 0) g_cnt = 0;
        const float* p = text + (size_t)b * T1 * CD + d;
        float s = 0.f;
#pragma unroll
        for (int t = 0; t < T1; t++) { float v = p[t * CD]; s += v * v; }
        float inv = 1.0f / sqrtf(s);
        int8_t* base = g_Asw + (((size_t)(b >> 1)) * NCH + (d >> 7)) * A_CH;
        uint32_t colb = d & 127;
#pragma unroll 4
        for (int t = 0; t < TL; t++) {
            int row = (b & 1) * 32 + t;
            base[SWZ(row * 128 + colb)] = to_s8(p[(t + 1) * CD] * inv);
        }
    } else {
        const float* p = video + (size_t)b * I1 * CD + d;
        float s = 0.f;
#pragma unroll 4
        for (int t = 0; t < I1; t++) { float v = p[t * CD]; s += v * v; }
        float inv = 1.0f / sqrtf(s);
        int8_t* base = g_Bsw + ((size_t)b * NCH + (d >> 7)) * B_CH;
        uint32_t colb = d & 127;
        for (int t = 0; t < I1; t++)
            base[SWZ(t * 128 + colb)] = to_s8(p[t * CD] * inv);
        for (int t = I1; t < IP; t++)
            base[SWZ(t * 128 + colb)] = 0;
    }
}

// ---------------------------------------------------------------------------
// ksim: CTA (qh,y): D[64,224] = A(64x512)*B(224x512)^T in s8->s32.
// 8 warps 2(M)x4(N), warp tile 32x56, K-chunks of 128 (4 x k32 steps),
// 3-stage bulk ring, occupancy 2. Fused max/mean epilogue + last-CTA loss.
// ---------------------------------------------------------------------------
#define SM_RMAX  0
#define SM_MBF   1024
#define SM_MBE   1088
#define SM_STG   2048
#define STG_SZ   (A_CH + B_CH)              // 36864
#define SM_TOTAL (SM_STG + 3 * STG_SZ)      // 112640

__global__ void __launch_bounds__(256, 2)
ksim(const int* __restrict__ amask, float* __restrict__ out) {
    extern __shared__ char smem[];
    __shared__ int lastflag;
    const uint32_t sb = smem_u32(smem);
    const int tid = threadIdx.x, wid = tid >> 5, lid = tid & 31;
    const int wm = wid & 1, wn = wid >> 1;
    const int qh = blockIdx.x, y = blockIdx.y;

    const int8_t* Asrc = g_Asw + (size_t)qh * NCH * A_CH;
    const int8_t* Bsrc = g_Bsw + (size_t)y * NCH * B_CH;

    if (tid == 0) {
#pragma unroll
        for (int s = 0; s < 3; s++) {
            mbar_init(sb + SM_MBF + 8 * s, 1);
            mbar_init(sb + SM_MBE + 8 * s, 8);
        }
    }
    __syncthreads();
    if (tid == 0) {
#pragma unroll
        for (int s = 0; s < 3; s++) {                 // prologue: chunks 0..2
            uint32_t mb = sb + SM_MBF + 8 * s;
            uint32_t st = sb + SM_STG + s * STG_SZ;
            mbar_expect(mb, STG_SZ);
            bulk_ld(st,        Asrc + (size_t)s * A_CH, A_CH, mb);
            bulk_ld(st + A_CH, Bsrc + (size_t)s * B_CH, B_CH, mb);
        }
    }

    int acc[2][7][4];
#pragma unroll
    for (int mi = 0; mi < 2; mi++)
#pragma unroll
        for (int nj = 0; nj < 7; nj++)
#pragma unroll
            for (int d = 0; d < 4; d++) acc[mi][nj][d] = 0;

    const int arow = 32 * wm + (lid & 15);
    const int brow = 56 * wn + (lid & 15);
    const int btr  = 56 * wn + 48 + (lid & 7);
    const int chi  = (lid >> 4) * 16;
    const int cht  = ((lid >> 3) & 1) * 16;

    int cs = 0;
    uint32_t ph = 0, eph = 0;

#pragma unroll 1
    for (int c = 0; c < NCH; c++) {
        const int s = cs;
        cs = (cs == 2) ? 0 : cs + 1;
        MBAR_WAIT(sb + SM_MBF + 8 * s, (ph >> s) & 1);
        ph ^= (1u << s);
        const uint32_t Abase = sb + SM_STG + s * STG_SZ;
        const uint32_t Bbase = Abase + A_CH;

#pragma unroll
        for (int ks = 0; ks < 4; ks++) {              // k32 steps within K=128
            const int kb = ks * 32;                   // byte offset within row
            uint32_t af[2][4];
#pragma unroll
            for (int mi = 0; mi < 2; mi++)
                ldm_x4(af[mi][0], af[mi][1], af[mi][2], af[mi][3],
                       Abase + SWZ((arow + 16 * mi) * 128 + kb + chi));
            uint32_t bf[3][4], bt[2];
#pragma unroll
            for (int ni = 0; ni < 3; ni++)
                ldm_x4(bf[ni][0], bf[ni][1], bf[ni][2], bf[ni][3],
                       Bbase + SWZ((brow + 16 * ni) * 128 + kb + chi));
            ldm_x2(bt[0], bt[1], Bbase + SWZ(btr * 128 + kb + cht));
#pragma unroll
            for (int mi = 0; mi < 2; mi++) {
#pragma unroll
                for (int ni = 0; ni < 3; ni++) {
                    mma_s8(acc[mi][2 * ni],     af[mi], bf[ni][0], bf[ni][2]);
                    mma_s8(acc[mi][2 * ni + 1], af[mi], bf[ni][1], bf[ni][3]);
                }
                mma_s8(acc[mi][6], af[mi], bt[0], bt[1]);
            }
        }
        if (lid == 0) mbar_arrive(sb + SM_MBE + 8 * s);

        if (tid == 0 && c < NCH - 3) {                // refill stage s, chunk c+3
            MBAR_WAIT(sb + SM_MBE + 8 * s, (eph >> s) & 1);
            eph ^= (1u << s);
            uint32_t mb = sb + SM_MBF + 8 * s;
            mbar_expect(mb, STG_SZ);
            bulk_ld(Abase,        Asrc + (size_t)(c + 3) * A_CH, A_CH, mb);
            bulk_ld(Abase + A_CH, Bsrc + (size_t)(c + 3) * B_CH, B_CH, mb);
        }
    }

    // ---- Epilogue: per-row int max over i (mask i>=197) -> masked mean over t
    float* rowmax = (float*)(smem + SM_RMAX);          // [64][4]
#pragma unroll
    for (int mi = 0; mi < 2; mi++)
#pragma unroll
        for (int h = 0; h < 2; h++) {
            int m = -2147483647;
#pragma unroll
            for (int nj = 0; nj < 7; nj++)
#pragma unroll
                for (int e = 0; e < 2; e++) {
                    int col = 56 * wn + 8 * nj + 2 * (lid & 3) + e;
                    int v = acc[mi][nj][2 * h + e];
                    if (col < I1) m = max(m, v);
                }
            m = max(m, __shfl_xor_sync(0xffffffffu, m, 1));
            m = max(m, __shfl_xor_sync(0xffffffffu, m, 2));
            if ((lid & 3) == 0) {
                int row = 32 * wm + 16 * mi + 8 * h + (lid >> 2);
                rowmax[4 * row + wn] = (float)m;
            }
        }
    __syncthreads();

    if (tid < 64) {
        int row = tid;
        float m = fmaxf(fmaxf(rowmax[4 * row], rowmax[4 * row + 1]),
                        fmaxf(rowmax[4 * row + 2], rowmax[4 * row + 3]));
        int xl = row >> 5, t = row & 31;
        int x = 2 * qh + xl;
        int mk = amask[x * T1 + 1 + t] != 0;
        float v = mk ? m * OSCALE : 0.f;
        float cnt = mk ? 1.f : 0.f;
#pragma unroll
        for (int o = 16; o > 0; o >>= 1) {
            v   += __shfl_xor_sync(0xffffffffu, v, o);
            cnt += __shfl_xor_sync(0xffffffffu, cnt, o);
        }
        if (t == 0) g_tti[x * NB + y] = v / fmaxf(cnt, 1e-6f);
    }
    __syncthreads();

    // ---- Last CTA computes the loss
    if (tid == 0) {
        __threadfence();
        lastflag = (atomicAdd(&g_cnt, 1) == NCTA - 1);
    }
    __syncthreads();
    if (lastflag) {
        __threadfence();
        float* sl = (float*)(smem + SM_RMAX);
#pragma unroll 1
        for (int rep = 0; rep < 8; rep++) {
            int x = 8 * wid + rep;
            const float* row = g_tti + x * NB;
            float e = expf(row[lid]) + expf(row[lid + 32]);
#pragma unroll
            for (int o = 16; o > 0; o >>= 1) e += __shfl_xor_sync(0xffffffffu, e, o);
            if (lid == 0) sl[x] = -logf(expf(row[x]) / e + 1e-20f);
        }
        __syncthreads();
        if (tid < 32) {
            float s = sl[lid] + sl[lid + 32];
#pragma unroll
            for (int o = 16; o > 0; o >>= 1) s += __shfl_xor_sync(0xffffffffu, s, o);
            if (lid == 0) out[0] = s * (1.0f / NB);
        }
    }
}

// ---------------------------------------------------------------------------
extern "C" void kernel_launch(void* const* d_in, const int* in_sizes, int n_in,
                              void* d_out, int out_size) {
    const float* text  = (const float*)d_in[0];
    const float* video = (const float*)d_in[1];
    const int*   mask  = (const int*)d_in[2];

    static int smem_set = 0;
    if (!smem_set) {
        cudaFuncSetAttribute(ksim, cudaFuncAttributeMaxDynamicSharedMemorySize, SM_TOTAL);
        smem_set = 1;
    }

    knorm<<<dim3(NB, 2), 512>>>(text, video);
    ksim<<<dim3(32, NB), 256, SM_TOTAL>>>(mask, (float*)d_out);
}

// round 11
// speedup vs baseline: 1.7406x; 1.0273x over previous
#include <cuda_runtime.h>
#include <cuda_bf16.h>
#include <math.h>
#include <stdint.h>

// Shapes
#define NB   64
#define T1   33
#define TL   32
#define I1   197
#define IP   224      // padded i
#define CD   512
#define TEMP 0.07f
#define QS   127.0f   // int8 quant scale (|v| <= 1 guaranteed by normalization)
#define OSCALE (TEMP / (QS * QS))
#define NCH  4        // K chunks of 128 (int8: 128B rows)
#define A_CH 8192     // A chunk image: 64 rows x 128B
#define B_CH 28672    // B chunk image: 224 rows x 128B
#define NCTA 2048     // 32 x 64

// Scratch: pre-swizzled, chunk-major int8 SMEM images
__device__ __align__(256) int8_t g_Asw[32 * NCH * A_CH];
__device__ __align__(256) int8_t g_Bsw[NB * NCH * B_CH];
__device__ float g_tti[NB * NB];
__device__ int   g_cnt;

// ---------------------------------------------------------------------------
// Portable PTX helpers
// ---------------------------------------------------------------------------
__device__ __forceinline__ uint32_t smem_u32(const void* p) {
    uint32_t a;
    asm("{ .reg .u64 t; cvta.to.shared.u64 t, %1; cvt.u32.u64 %0, t; }"
        : "=r"(a) : "l"(p));
    return a;
}
#define SWZ(o) ((o) ^ ((((uint32_t)(o)) >> 3) & 0x70u))

__device__ __forceinline__ void bulk_ld(uint32_t dst, const void* src,
                                        uint32_t bytes, uint32_t mbar) {
    asm volatile(
        "cp.async.bulk.shared::cluster.global.mbarrier::complete_tx::bytes "
        "[%0], [%1], %2, [%3];"
        :: "r"(dst), "l"(src), "r"(bytes), "r"(mbar) : "memory");
}
__device__ __forceinline__ void mbar_init(uint32_t m, uint32_t cnt) {
    asm volatile("mbarrier.init.shared.b64 [%0], %1;" :: "r"(m), "r"(cnt) : "memory");
}
__device__ __forceinline__ void mbar_expect(uint32_t m, uint32_t bytes) {
    asm volatile("mbarrier.arrive.expect_tx.shared.b64 _, [%0], %1;"
                 :: "r"(m), "r"(bytes) : "memory");
}
__device__ __forceinline__ void mbar_arrive(uint32_t m) {
    asm volatile("mbarrier.arrive.shared.b64 _, [%0];" :: "r"(m) : "memory");
}
#define MBAR_WAIT(addr, par) do {                                               \
    uint32_t _m = (addr), _p = (par), _d;                                       \
    asm volatile("{\n\t.reg .pred p;\n\t"                                       \
        "mbarrier.try_wait.parity.acquire.cta.shared::cta.b64 p, [%1], %2;\n\t" \
        "selp.b32 %0, 1, 0, p;\n\t}" : "=r"(_d) : "r"(_m), "r"(_p) : "memory"); \
    if (!_d) {                                                                  \
        asm volatile("{\n\t.reg .pred P1;\n\tWL_%=:\n\t"                        \
            "mbarrier.try_wait.parity.acquire.cta.shared::cta.b64 P1, [%0], %1, 0x989680;\n\t" \
            "@P1 bra.uni WD_%=;\n\tbra.uni WL_%=;\n\tWD_%=:\n\t}"               \
            :: "r"(_m), "r"(_p) : "memory");                                    \
    }                                                                           \
} while (0)

__device__ __forceinline__ void ldm_x4(uint32_t* r, uint32_t a) {
    asm volatile("ldmatrix.sync.aligned.m8n8.x4.shared.b16 {%0,%1,%2,%3}, [%4];"
                 : "=r"(r[0]), "=r"(r[1]), "=r"(r[2]), "=r"(r[3]) : "r"(a));
}
__device__ __forceinline__ void ldm_x2(uint32_t* r, uint32_t a) {
    asm volatile("ldmatrix.sync.aligned.m8n8.x2.shared.b16 {%0,%1}, [%2];"
                 : "=r"(r[0]), "=r"(r[1]) : "r"(a));
}
// int8 IMMA, K=32 per instruction (sm_75+ base PTX, native SASS lineage)
__device__ __forceinline__ void mma_s8(int* d, const uint32_t* a,
                                       uint32_t b0, uint32_t b1) {
    asm volatile(
        "mma.sync.aligned.m16n8k32.row.col.s32.s8.s8.s32 "
        "{%0,%1,%2,%3}, {%4,%5,%6,%7}, {%8,%9}, {%0,%1,%2,%3};"
        : "+r"(d[0]), "+r"(d[1]), "+r"(d[2]), "+r"(d[3])
        : "r"(a[0]), "r"(a[1]), "r"(a[2]), "r"(a[3]), "r"(b0), "r"(b1));
}

__device__ __forceinline__ int8_t to_s8(float v) {
    return (int8_t)__float2int_rn(v * QS);
}

// ---------------------------------------------------------------------------
// knorm: grid (64,2), block 512. by==0 -> text, by==1 -> video. int8 output,
// written directly in swizzled chunk-major (K=128) SMEM image.
// ---------------------------------------------------------------------------
__global__ void knorm(const float* __restrict__ text, const float* __restrict__ video) {
    int b = blockIdx.x, d = threadIdx.x;
    if (blockIdx.y == 0) {
        if (b == 0 && d == 0) g_cnt = 0;
        const float* p = text + (size_t)b * T1 * CD + d;
        float s = 0.f;
#pragma unroll
        for (int t = 0; t < T1; t++) { float v = p[t * CD]; s += v * v; }
        float inv = 1.0f / sqrtf(s);
        int8_t* base = g_Asw + (((size_t)(b >> 1)) * NCH + (d >> 7)) * A_CH;
        uint32_t colb = d & 127;
#pragma unroll 4
        for (int t = 0; t < TL; t++) {
            int row = (b & 1) * 32 + t;
            base[SWZ(row * 128 + colb)] = to_s8(p[(t + 1) * CD] * inv);
        }
    } else {
        const float* p = video + (size_t)b * I1 * CD + d;
        float s0 = 0.f, s1 = 0.f;                 // dual accumulators: 2x MLP
#pragma unroll 14
        for (int t = 0; t < 196; t += 2) {
            float v0 = p[t * CD], v1 = p[(t + 1) * CD];
            s0 += v0 * v0; s1 += v1 * v1;
        }
        { float v = p[196 * CD]; s0 += v * v; }
        float inv = 1.0f / sqrtf(s0 + s1);
        int8_t* base = g_Bsw + ((size_t)b * NCH + (d >> 7)) * B_CH;
        uint32_t colb = d & 127;
#pragma unroll 4
        for (int t = 0; t < I1; t++)
            base[SWZ(t * 128 + colb)] = to_s8(p[t * CD] * inv);
        for (int t = I1; t < IP; t++)
            base[SWZ(t * 128 + colb)] = 0;
    }
}

// ---------------------------------------------------------------------------
// ksim: CTA (qh,y): D[64,224] = A(64x512)*B(224x512)^T in s8->s32.
// 8 warps 2(M)x4(N), warp tile 32x56, K-chunks of 128 (4 x k32 steps),
// 3-stage bulk ring, occupancy 2. Fragment DOUBLE-BUFFERING across ks:
// frags[ks+1] load overlaps IMMAs[ks]. Fused max/mean epilogue + last-CTA loss.
// ---------------------------------------------------------------------------
#define SM_RMAX  0
#define SM_MBF   1024
#define SM_MBE   1088
#define SM_STG   2048
#define STG_SZ   (A_CH + B_CH)              // 36864
#define SM_TOTAL (SM_STG + 3 * STG_SZ)      // 112640

__global__ void __launch_bounds__(256, 2)
ksim(const int* __restrict__ amask, float* __restrict__ out) {
    extern __shared__ char smem[];
    __shared__ int lastflag;
    const uint32_t sb = smem_u32(smem);
    const int tid = threadIdx.x, wid = tid >> 5, lid = tid & 31;
    const int wm = wid & 1, wn = wid >> 1;
    const int qh = blockIdx.x, y = blockIdx.y;

    const int8_t* Asrc = g_Asw + (size_t)qh * NCH * A_CH;
    const int8_t* Bsrc = g_Bsw + (size_t)y * NCH * B_CH;

    if (tid == 0) {
#pragma unroll
        for (int s = 0; s < 3; s++) {
            mbar_init(sb + SM_MBF + 8 * s, 1);
            mbar_init(sb + SM_MBE + 8 * s, 8);
        }
    }
    __syncthreads();
    if (tid == 0) {
#pragma unroll
        for (int s = 0; s < 3; s++) {                 // prologue: chunks 0..2
            uint32_t mb = sb + SM_MBF + 8 * s;
            uint32_t st = sb + SM_STG + s * STG_SZ;
            mbar_expect(mb, STG_SZ);
            bulk_ld(st,        Asrc + (size_t)s * A_CH, A_CH, mb);
            bulk_ld(st + A_CH, Bsrc + (size_t)s * B_CH, B_CH, mb);
        }
    }

    int acc[2][7][4];
#pragma unroll
    for (int mi = 0; mi < 2; mi++)
#pragma unroll
        for (int nj = 0; nj < 7; nj++)
#pragma unroll
            for (int d = 0; d < 4; d++) acc[mi][nj][d] = 0;

    const int arow = 32 * wm + (lid & 15);
    const int brow = 56 * wn + (lid & 15);
    const int btr  = 56 * wn + 48 + (lid & 7);
    const int chi  = (lid >> 4) * 16;
    const int cht  = ((lid >> 3) & 1) * 16;

    // Double-buffered fragments
    uint32_t af[2][2][4];     // [buf][mi][4]
    uint32_t bf[2][3][4];     // [buf][ni][4]
    uint32_t bt[2][2];        // [buf][2]

    int cs = 0;
    uint32_t ph = 0, eph = 0;

#pragma unroll 1
    for (int c = 0; c < NCH; c++) {
        const int s = cs;
        cs = (cs == 2) ? 0 : cs + 1;
        MBAR_WAIT(sb + SM_MBF + 8 * s, (ph >> s) & 1);
        ph ^= (1u << s);
        const uint32_t Abase = sb + SM_STG + s * STG_SZ;
        const uint32_t Bbase = Abase + A_CH;

        // Preload ks=0 fragments into buf 0
#pragma unroll
        for (int mi = 0; mi < 2; mi++)
            ldm_x4(af[0][mi], Abase + SWZ((arow + 16 * mi) * 128 + chi));
#pragma unroll
        for (int ni = 0; ni < 3; ni++)
            ldm_x4(bf[0][ni], Bbase + SWZ((brow + 16 * ni) * 128 + chi));
        ldm_x2(bt[0], Bbase + SWZ(btr * 128 + cht));

#pragma unroll
        for (int ks = 0; ks < 4; ks++) {
            const int cb = ks & 1, nb = cb ^ 1;
            if (ks < 3) {                              // prefetch ks+1 into nb
                const int kb = (ks + 1) * 32;
#pragma unroll
                for (int mi = 0; mi < 2; mi++)
                    ldm_x4(af[nb][mi], Abase + SWZ((arow + 16 * mi) * 128 + kb + chi));
#pragma unroll
                for (int ni = 0; ni < 3; ni++)
                    ldm_x4(bf[nb][ni], Bbase + SWZ((brow + 16 * ni) * 128 + kb + chi));
                ldm_x2(bt[nb], Bbase + SWZ(btr * 128 + kb + cht));
            }
#pragma unroll
            for (int mi = 0; mi < 2; mi++) {
#pragma unroll
                for (int ni = 0; ni < 3; ni++) {
                    mma_s8(acc[mi][2 * ni],     af[cb][mi], bf[cb][ni][0], bf[cb][ni][2]);
                    mma_s8(acc[mi][2 * ni + 1], af[cb][mi], bf[cb][ni][1], bf[cb][ni][3]);
                }
                mma_s8(acc[mi][6], af[cb][mi], bt[cb][0], bt[cb][1]);
            }
        }
        if (lid == 0) mbar_arrive(sb + SM_MBE + 8 * s);

        if (tid == 0 && c < NCH - 3) {                // refill stage s, chunk c+3
            MBAR_WAIT(sb + SM_MBE + 8 * s, (eph >> s) & 1);
            eph ^= (1u << s);
            uint32_t mb = sb + SM_MBF + 8 * s;
            mbar_expect(mb, STG_SZ);
            bulk_ld(Abase,        Asrc + (size_t)(c + 3) * A_CH, A_CH, mb);
            bulk_ld(Abase + A_CH, Bsrc + (size_t)(c + 3) * B_CH, B_CH, mb);
        }
    }

    // ---- Epilogue: per-row int max over i (mask i>=197) -> masked mean over t
    float* rowmax = (float*)(smem + SM_RMAX);          // [64][4]
#pragma unroll
    for (int mi = 0; mi < 2; mi++)
#pragma unroll
        for (int h = 0; h < 2; h++) {
            int m = -2147483647;
#pragma unroll
            for (int nj = 0; nj < 7; nj++)
#pragma unroll
                for (int e = 0; e < 2; e++) {
                    int col = 56 * wn + 8 * nj + 2 * (lid & 3) + e;
                    int v = acc[mi][nj][2 * h + e];
                    if (col < I1) m = max(m, v);
                }
            m = max(m, __shfl_xor_sync(0xffffffffu, m, 1));
            m = max(m, __shfl_xor_sync(0xffffffffu, m, 2));
            if ((lid & 3) == 0) {
                int row = 32 * wm + 16 * mi + 8 * h + (lid >> 2);
                rowmax[4 * row + wn] = (float)m;
            }
        }
    __syncthreads();

    if (tid < 64) {
        int row = tid;
        float m = fmaxf(fmaxf(rowmax[4 * row], rowmax[4 * row + 1]),
                        fmaxf(rowmax[4 * row + 2], rowmax[4 * row + 3]));
        int xl = row >> 5, t = row & 31;
        int x = 2 * qh + xl;
        int mk = amask[x * T1 + 1 + t] != 0;
        float v = mk ? m * OSCALE : 0.f;
        float cnt = mk ? 1.f : 0.f;
#pragma unroll
        for (int o = 16; o > 0; o >>= 1) {
            v   += __shfl_xor_sync(0xffffffffu, v, o);
            cnt += __shfl_xor_sync(0xffffffffu, cnt, o);
        }
        if (t == 0) g_tti[x * NB + y] = v / fmaxf(cnt, 1e-6f);
    }
    __syncthreads();

    // ---- Last CTA computes the loss
    if (tid == 0) {
        __threadfence();
        lastflag = (atomicAdd(&g_cnt, 1) == NCTA - 1);
    }
    __syncthreads();
    if (lastflag) {
        __threadfence();
        float* sl = (float*)(smem + SM_RMAX);
#pragma unroll 1
        for (int rep = 0; rep < 8; rep++) {
            int x = 8 * wid + rep;
            const float* row = g_tti + x * NB;
            float e = expf(row[lid]) + expf(row[lid + 32]);
#pragma unroll
            for (int o = 16; o > 0; o >>= 1) e += __shfl_xor_sync(0xffffffffu, e, o);
            if (lid == 0) sl[x] = -logf(expf(row[x]) / e + 1e-20f);
        }
        __syncthreads();
        if (tid < 32) {
            float s = sl[lid] + sl[lid + 32];
#pragma unroll
            for (int o = 16; o > 0; o >>= 1) s += __shfl_xor_sync(0xffffffffu, s, o);
            if (lid == 0) out[0] = s * (1.0f / NB);
        }
    }
}

// ---------------------------------------------------------------------------
extern "C" void kernel_launch(void* const* d_in, const int* in_sizes, int n_in,
                              void* d_out, int out_size) {
    const float* text  = (const float*)d_in[0];
    const float* video = (const float*)d_in[1];
    const int*   mask  = (const int*)d_in[2];

    static int smem_set = 0;
    if (!smem_set) {
        cudaFuncSetAttribute(ksim, cudaFuncAttributeMaxDynamicSharedMemorySize, SM_TOTAL);
        smem_set = 1;
    }

    knorm<<<dim3(NB, 2), 512>>>(text, video);
    ksim<<<dim3(32, NB), 256, SM_TOTAL>>>(mask, (float*)d_out);
}